// round 15
// baseline (speedup 1.0000x reference)
#include <cuda_runtime.h>
#include <cuda_fp16.h>
#include <math.h>
#include <stdint.h>

#define NSAMP 4096
#define DIN   1536
#define DMLP  512
#define FD    256
#define NCLS  10000
#define KP1   DIN       // 1536 (plain fp16)
#define KP2   DMLP      // 512  (plain fp16)
#define KPS   FD        // 256  (plain fp16)
#define MAXDUP 64

// ---- static device scratch ----
__device__ float g_hpart[4][NSAMP * DMLP];
__device__ float g_fpart[4][NSAMP * FD];
__device__ float g_h[NSAMP * DMLP];
__device__ float g_psum[256 * DMLP];
__device__ float g_psq[256 * DMLP];
__device__ float g_scale[DMLP];
__device__ float g_shift[DMLP];
__device__ float g_feat[NSAMP * FD];
__device__ int   g_cnt[NCLS];
__device__ int   g_bucket[NCLS * MAXDUP];

__device__ __align__(16) __half g_A1[(size_t)NSAMP * KP1];
__device__ __align__(16) __half g_B1[(size_t)DMLP * KP1];   // W1^T
__device__ __align__(16) __half g_A2[(size_t)NSAMP * KP2];
__device__ __align__(16) __half g_B2[(size_t)FD * KP2];     // W2^T
__device__ __align__(16) __half g_feat2[(size_t)NSAMP * KPS];
__device__ __align__(16) __half g_mem2[(size_t)NCLS * KPS];

// ============================================================
// conversions
// ============================================================
__global__ void conv_A1_kernel(const float* __restrict__ A)
{
    int idx = blockIdx.x * 256 + threadIdx.x;
    if (idx < NCLS) g_cnt[idx] = 0;
    if (idx >= NSAMP * DIN) return;
    g_A1[idx] = __float2half_rn(A[idx]);
}

// coalesced transpose: W[ROWS][COLS] (fp32) -> dst[COLS][ROWS] (fp16)
// DST: 0 -> g_B1, 1 -> g_B2  (selected in DEVICE code; no __device__ symbol
// is ever passed as a host-side kernel argument)
template<int ROWS, int COLS, int DST>
__global__ __launch_bounds__(256) void convT_kernel(const float* __restrict__ W)
{
    __half* __restrict__ out = (DST == 0) ? g_B1 : g_B2;
    __shared__ __half tile[32][33];
    const int bx = blockIdx.x;
    const int by = blockIdx.y;
    const int t = threadIdx.x;
    const int tr = t >> 5, tc = t & 31;
#pragma unroll
    for (int i = 0; i < 4; i++) {
        int r = by * 32 + tr + i * 8;
        int c = bx * 32 + tc;
        tile[tr + i * 8][tc] = __float2half_rn(W[(size_t)r * COLS + c]);
    }
    __syncthreads();
#pragma unroll
    for (int i = 0; i < 4; i++) {
        int c = bx * 32 + tr + i * 8;
        int r = by * 32 + tc;
        out[(size_t)c * ROWS + r] = tile[tc][tr + i * 8];
    }
}

__global__ void conv_A2_kernel()
{
    int idx = blockIdx.x * 256 + threadIdx.x;
    if (idx >= NSAMP * DMLP) return;
    int c = idx & (DMLP - 1);
    float x = fmaxf(g_h[idx] * g_scale[c] + g_shift[c], 0.f);
    g_A2[idx] = __float2half_rn(x);
}

// ============================================================
// rank/bucket build: deterministic inverted index over labels
// ============================================================
__global__ __launch_bounds__(256) void rank_kernel(const int* __restrict__ label)
{
    __shared__ int sl[NSAMP];
    const int t = threadIdx.x;
    for (int i = t; i < NSAMP; i += 256) sl[i] = label[i];
    __syncthreads();
    const int i = blockIdx.x * 256 + t;
    const int my = sl[i];
    int r = 0, tot = 0;
#pragma unroll 8
    for (int j = 0; j < NSAMP; j++) {
        int eq = (sl[j] == my) ? 1 : 0;
        tot += eq;
        r += (j < i) ? eq : 0;
    }
    if (r == 0) g_cnt[my] = tot;
    if (r < MAXDUP) g_bucket[my * MAXDUP + r] = i;
}

// ============================================================
// asm helpers
// ============================================================
__device__ __forceinline__ void mma_f16(float c[4],
    unsigned a0, unsigned a1, unsigned a2, unsigned a3,
    unsigned b0, unsigned b1)
{
    asm volatile(
        "mma.sync.aligned.m16n8k16.row.col.f32.f16.f16.f32 "
        "{%0,%1,%2,%3},{%4,%5,%6,%7},{%8,%9},{%0,%1,%2,%3};\n"
        : "+f"(c[0]), "+f"(c[1]), "+f"(c[2]), "+f"(c[3])
        : "r"(a0), "r"(a1), "r"(a2), "r"(a3), "r"(b0), "r"(b1));
}

__device__ __forceinline__ void cp_async16(void* dst, const void* src)
{
    unsigned s = (unsigned)__cvta_generic_to_shared(dst);
    asm volatile("cp.async.cg.shared.global [%0], [%1], 16;\n" :: "r"(s), "l"(src));
}
__device__ __forceinline__ void cp_commit() { asm volatile("cp.async.commit_group;\n"); }
template<int W>
__device__ __forceinline__ void cp_wait() { asm volatile("cp.async.wait_group %0;\n" :: "n"(W) : "memory"); }

__device__ __forceinline__ void ldsm_x4(unsigned& r0, unsigned& r1,
                                        unsigned& r2, unsigned& r3, const void* p)
{
    unsigned a = (unsigned)__cvta_generic_to_shared(p);
    asm volatile("ldmatrix.sync.aligned.m8n8.x4.shared.b16 {%0,%1,%2,%3}, [%4];\n"
        : "=r"(r0), "=r"(r1), "=r"(r2), "=r"(r3) : "r"(a));
}

// ============================================================
// pipelined fp16 MMA GEMM: 128x128 block, BK=64, warp tile 64x32,
// 2-stage dynamic-smem cp.async pipeline (R12-proven, two barriers/iter).
// WHICH: 0 = gemm1 -> g_hpart[z] ; 1 = sim -> Cout ; 2 = gemm2 -> g_fpart[z]
// ============================================================
#define GEMM_SMEM (2 * 36864)

template<int KP, int NK, int WHICH>
__global__ __launch_bounds__(256, 2) void mma_gemm_kernel(float* __restrict__ Cout)
{
    constexpr int BK = 64;
    constexpr int LDS_ = 72;
    constexpr int WTN = 32;
    constexpr int NTI = 4;
    constexpr int STG = 18432;
    constexpr int BOFF = 9216;
    constexpr int Nreal = (WHICH == 0) ? DMLP : (WHICH == 1 ? NCLS : FD);
    constexpr int ldc   = Nreal;

    const __half* __restrict__ A =
        (WHICH == 0) ? g_A1 : (WHICH == 1 ? g_feat2 : g_A2);
    const __half* __restrict__ B =
        (WHICH == 0) ? g_B1 : (WHICH == 1 ? g_mem2 : g_B2);
    float* __restrict__ C =
        (WHICH == 0) ? g_hpart[blockIdx.z] : (WHICH == 1 ? Cout : g_fpart[blockIdx.z]);

    const int ktb = (WHICH == 1) ? 0 : blockIdx.z * NK;

    extern __shared__ __align__(16) __half sm[];

    const int tid = threadIdx.x;
    const int wid = tid >> 5, lane = tid & 31;
    const int wm = wid >> 2, wn = wid & 3;
    const int bm = blockIdx.y * 128;
    const int bn = blockIdx.x * 128;

    const int lr0 = tid >> 3, lch = (tid & 7) * 8;
    auto load_stage = [&](int kt, int s) {
        __half* as = sm + s * STG;
        __half* bs = sm + s * STG + BOFF;
        const int kc = (ktb + kt) * BK + lch;
#pragma unroll
        for (int i = 0; i < 4; i++) {
            int r = lr0 + 32 * i;
            cp_async16(as + r * LDS_ + lch, A + (size_t)(bm + r) * KP + kc);
        }
#pragma unroll
        for (int i = 0; i < 4; i++) {
            int r = lr0 + 32 * i;
            int gn = bn + r;
            if (WHICH == 1) gn = (gn < NCLS) ? gn : (NCLS - 1);
            cp_async16(bs + r * LDS_ + lch, B + (size_t)gn * KP + kc);
        }
        cp_commit();
    };

    float acc[4][NTI][4];
#pragma unroll
    for (int i = 0; i < 4; i++)
#pragma unroll
        for (int j = 0; j < NTI; j++)
#pragma unroll
            for (int t = 0; t < 4; t++) acc[i][j][t] = 0.f;

    load_stage(0, 0);

    const int arow = lane & 15, ahalf = (lane >> 4) * 8;
    const int bl = lane & 7, bsel = lane >> 3;

    for (int kt = 0; kt < NK; kt++) {
        const int s = kt & 1;
        cp_wait<0>();
        __syncthreads();

        if (kt + 1 < NK) load_stage(kt + 1, s ^ 1);

        const __half* as = sm + s * STG;
        const __half* bs = sm + s * STG + BOFF;
#pragma unroll
        for (int ks = 0; ks < 4; ks++) {
            const int k0 = ks * 16;
            unsigned af[4][4];
#pragma unroll
            for (int i = 0; i < 4; i++)
                ldsm_x4(af[i][0], af[i][1], af[i][2], af[i][3],
                        as + (wm * 64 + i * 16 + arow) * LDS_ + k0 + ahalf);
            unsigned bfr[NTI][2];
#pragma unroll
            for (int p = 0; p < NTI / 2; p++) {
                int n = wn * WTN + (p * 2 + (bsel >> 1)) * 8 + bl;
                ldsm_x4(bfr[p * 2][0], bfr[p * 2][1], bfr[p * 2 + 1][0], bfr[p * 2 + 1][1],
                        bs + n * LDS_ + k0 + (bsel & 1) * 8);
            }
#pragma unroll
            for (int i = 0; i < 4; i++)
#pragma unroll
                for (int j = 0; j < NTI; j++)
                    mma_f16(acc[i][j], af[i][0], af[i][1], af[i][2], af[i][3],
                            bfr[j][0], bfr[j][1]);
        }
        __syncthreads();
    }

    const int g = lane >> 2, q2 = (lane & 3) * 2;
#pragma unroll
    for (int i = 0; i < 4; i++) {
        int m0 = bm + wm * 64 + i * 16 + g;
#pragma unroll
        for (int j = 0; j < NTI; j++) {
            int n0 = bn + wn * WTN + j * 8 + q2;
            if (WHICH != 1 || n0 < Nreal) {
                *(float2*)(C + (size_t)m0 * ldc + n0) =
                    make_float2(acc[i][j][0], acc[i][j][1]);
                *(float2*)(C + (size_t)(m0 + 8) * ldc + n0) =
                    make_float2(acc[i][j][2], acc[i][j][3]);
            }
        }
    }
}

// ============================================================
// split-K reduce (x4) + b1 bias + BN partial stats
// ============================================================
__global__ __launch_bounds__(512) void bn_reduce_partial_kernel(
    const float* __restrict__ b1)
{
    const int b = blockIdx.x, c = threadIdx.x;
    const float bias = b1[c];
    float s = 0.f, ss = 0.f;
#pragma unroll
    for (int r = 0; r < 16; r++) {
        size_t i = (size_t)(b * 16 + r) * DMLP + c;
        float v = g_hpart[0][i] + g_hpart[1][i] + g_hpart[2][i] + g_hpart[3][i] + bias;
        g_h[i] = v;
        s += v; ss += v * v;
    }
    g_psum[b * DMLP + c] = s;
    g_psq[b * DMLP + c] = ss;
}

__global__ __launch_bounds__(512) void bn_final_kernel(
    const float* __restrict__ gamma, const float* __restrict__ beta)
{
    const int c = threadIdx.x;
    float s = 0.f, ss = 0.f;
#pragma unroll 8
    for (int b = 0; b < 256; b++) { s += g_psum[b * DMLP + c]; ss += g_psq[b * DMLP + c]; }
    float mu = s * (1.0f / NSAMP);
    float var = ss * (1.0f / NSAMP) - mu * mu;
    float sc = gamma[c] * rsqrtf(var + 1e-5f);
    g_scale[c] = sc;
    g_shift[c] = beta[c] - mu * sc;
}

// ============================================================
// gemm2 split-K reduce + b2 bias + L2 norm + write g_feat & fp16 g_feat2
// ============================================================
__global__ __launch_bounds__(256) void norm_kernel(const float* __restrict__ b2)
{
    const int w = threadIdx.x >> 5, lane = threadIdx.x & 31;
    const int row = blockIdx.x * 8 + w;
    const size_t off = (size_t)row * FD;
    float vals[8];
    float ssq = 0.f;
#pragma unroll
    for (int j = 0; j < 8; j++) {
        int k = (j < 4) ? lane * 4 + j : 128 + lane * 4 + (j - 4);
        float v = g_fpart[0][off + k] + g_fpart[1][off + k]
                + g_fpart[2][off + k] + g_fpart[3][off + k] + b2[k];
        vals[j] = v;
        ssq += v * v;
    }
#pragma unroll
    for (int o = 16; o; o >>= 1) ssq += __shfl_xor_sync(0xffffffffu, ssq, o);
    float inv = 1.0f / fmaxf(sqrtf(ssq), 1e-12f);
#pragma unroll
    for (int j = 0; j < 8; j++) vals[j] *= inv;
    float* p = g_feat + off;
    *(float4*)(p + lane * 4)       = make_float4(vals[0], vals[1], vals[2], vals[3]);
    *(float4*)(p + 128 + lane * 4) = make_float4(vals[4], vals[5], vals[6], vals[7]);
    __half* q = g_feat2 + off;
#pragma unroll
    for (int j = 0; j < 8; j++) {
        int k = (j < 4) ? lane * 4 + j : 128 + lane * 4 + (j - 4);
        q[k] = __float2half_rn(vals[j]);
    }
}

// ============================================================
// Memory update via inverted index: warp per class, walk own sample list
// ============================================================
__global__ __launch_bounds__(256) void memupd_kernel(const float* __restrict__ mem0)
{
    const int w = threadIdx.x >> 5, lane = threadIdx.x & 31;
    const int k = blockIdx.x * 8 + w;
    if (k >= NCLS) return;

    float pt[8];
#pragma unroll
    for (int j = 0; j < 8; j++) pt[j] = mem0[(size_t)k * FD + lane + j * 32];

    const int n = g_cnt[k];
    for (int r = 0; r < n; r++) {
        int i = g_bucket[k * MAXDUP + r];
        const float* f = g_feat + (size_t)i * FD;
        float ssq = 0.f;
#pragma unroll
        for (int j = 0; j < 8; j++) {
            pt[j] = 0.9f * pt[j] + 0.1f * f[lane + j * 32];
            ssq += pt[j] * pt[j];
        }
#pragma unroll
        for (int o = 16; o; o >>= 1) ssq += __shfl_xor_sync(0xffffffffu, ssq, o);
        float inv = 1.0f / fmaxf(sqrtf(ssq), 1e-12f);
#pragma unroll
        for (int j = 0; j < 8; j++) pt[j] *= inv;
    }
    __half* q = g_mem2 + (size_t)k * KPS;
#pragma unroll
    for (int j = 0; j < 8; j++) q[lane + j * 32] = __float2half_rn(pt[j]);
}

// ============================================================
// launch
// ============================================================
extern "C" void kernel_launch(void* const* d_in, const int* in_sizes, int n_in,
                              void* d_out, int out_size)
{
    const float* feat_in = (const float*)d_in[0];
    const int*   label   = (const int*)d_in[1];
    const float* W1      = (const float*)d_in[2];
    const float* b1      = (const float*)d_in[3];
    const float* gamma   = (const float*)d_in[4];
    const float* beta    = (const float*)d_in[5];
    const float* W2      = (const float*)d_in[6];
    const float* b2      = (const float*)d_in[7];
    const float* mem0    = (const float*)d_in[8];
    float* out = (float*)d_out;

    cudaFuncSetAttribute(mma_gemm_kernel<KP1, 6, 0>,
                         cudaFuncAttributeMaxDynamicSharedMemorySize, GEMM_SMEM);
    cudaFuncSetAttribute(mma_gemm_kernel<KP2, 2, 2>,
                         cudaFuncAttributeMaxDynamicSharedMemorySize, GEMM_SMEM);
    cudaFuncSetAttribute(mma_gemm_kernel<KPS, 4, 1>,
                         cudaFuncAttributeMaxDynamicSharedMemorySize, GEMM_SMEM);

    conv_A1_kernel<<<(NSAMP * DIN + 255) / 256, 256>>>(feat_in);   // + zero g_cnt
    convT_kernel<DIN, DMLP, 0><<<dim3(DMLP / 32, DIN / 32), 256>>>(W1);
    convT_kernel<DMLP, FD, 1><<<dim3(FD / 32, DMLP / 32), 256>>>(W2);
    rank_kernel<<<NSAMP / 256, 256>>>(label);

    // GEMM1 split-K x4 (fp16, BK=64): NK = 1536/(4*64) = 6
    mma_gemm_kernel<KP1, 6, 0>
        <<<dim3(DMLP / 128, NSAMP / 128, 4), 256, GEMM_SMEM>>>(nullptr);

    bn_reduce_partial_kernel<<<256, 512>>>(b1);
    bn_final_kernel<<<1, 512>>>(gamma, beta);
    conv_A2_kernel<<<(NSAMP * DMLP + 255) / 256, 256>>>();

    // GEMM2 split-K x4 (fp16, BK=64): NK = 512/(4*64) = 2
    mma_gemm_kernel<KP2, 2, 2>
        <<<dim3(FD / 128, NSAMP / 128, 4), 256, GEMM_SMEM>>>(nullptr);
    norm_kernel<<<NSAMP / 8, 256>>>(b2);

    memupd_kernel<<<(NCLS + 7) / 8, 256>>>(mem0);

    // Sim GEMM (fp16, BK=64): NK = 256/64 = 4
    mma_gemm_kernel<KPS, 4, 1>
        <<<dim3((NCLS + 127) / 128, NSAMP / 128, 1), 256, GEMM_SMEM>>>(out);
}

// round 16
// speedup vs baseline: 1.2503x; 1.2503x over previous
#include <cuda_runtime.h>
#include <cuda_fp16.h>
#include <math.h>
#include <stdint.h>

#define NSAMP 4096
#define DIN   1536
#define DMLP  512
#define FD    256
#define NCLS  10000
#define KP1   DIN       // 1536 (plain fp16)
#define KP2   DMLP      // 512  (plain fp16)
#define KPS   FD        // 256  (plain fp16)
#define MAXDUP 64

// ---- static device scratch ----
__device__ float g_hpart[4][NSAMP * DMLP];
__device__ float g_fpart[4][NSAMP * FD];
__device__ float g_h[NSAMP * DMLP];
__device__ float g_psum[256 * DMLP];
__device__ float g_psq[256 * DMLP];
__device__ float g_scale[DMLP];
__device__ float g_shift[DMLP];
__device__ float g_feat[NSAMP * FD];
__device__ int   g_cnt[NCLS];
__device__ int   g_bucket[NCLS * MAXDUP];

__device__ __align__(16) __half g_A1[(size_t)NSAMP * KP1];
__device__ __align__(16) __half g_B1[(size_t)DMLP * KP1];   // W1^T
__device__ __align__(16) __half g_A2[(size_t)NSAMP * KP2];
__device__ __align__(16) __half g_B2[(size_t)FD * KP2];     // W2^T
__device__ __align__(16) __half g_feat2[(size_t)NSAMP * KPS];
__device__ __align__(16) __half g_mem2[(size_t)NCLS * KPS];

// ============================================================
// conversions
// ============================================================
__global__ void conv_A1_kernel(const float* __restrict__ A)
{
    int idx = blockIdx.x * 256 + threadIdx.x;
    if (idx < NCLS) g_cnt[idx] = 0;
    if (idx >= NSAMP * DIN) return;
    g_A1[idx] = __float2half_rn(A[idx]);
}

// coalesced transpose: W[ROWS][COLS] (fp32) -> dst[COLS][ROWS] (fp16)
// DST selected in device code (never pass __device__ symbols as host args!)
template<int ROWS, int COLS, int DST>
__global__ __launch_bounds__(256) void convT_kernel(const float* __restrict__ W)
{
    __half* __restrict__ out = (DST == 0) ? g_B1 : g_B2;
    __shared__ __half tile[32][33];
    const int bx = blockIdx.x;
    const int by = blockIdx.y;
    const int t = threadIdx.x;
    const int tr = t >> 5, tc = t & 31;
#pragma unroll
    for (int i = 0; i < 4; i++) {
        int r = by * 32 + tr + i * 8;
        int c = bx * 32 + tc;
        tile[tr + i * 8][tc] = __float2half_rn(W[(size_t)r * COLS + c]);
    }
    __syncthreads();
#pragma unroll
    for (int i = 0; i < 4; i++) {
        int c = bx * 32 + tr + i * 8;
        int r = by * 32 + tc;
        out[(size_t)c * ROWS + r] = tile[tc][tr + i * 8];
    }
}

__global__ void conv_A2_kernel()
{
    int idx = blockIdx.x * 256 + threadIdx.x;
    if (idx >= NSAMP * DMLP) return;
    int c = idx & (DMLP - 1);
    float x = fmaxf(g_h[idx] * g_scale[c] + g_shift[c], 0.f);
    g_A2[idx] = __float2half_rn(x);
}

// ============================================================
// rank/bucket build: one WARP per sample, lanes stride the labels.
// Deterministic inverted index: bucket[k][r] = i where r = #{j<i: l_j=l_i}
// ============================================================
__global__ __launch_bounds__(256) void rank_kernel(const int* __restrict__ label)
{
    __shared__ int sl[NSAMP];
    const int t = threadIdx.x;
    for (int i = t; i < NSAMP; i += 256) sl[i] = label[i];
    __syncthreads();

    const int w = t >> 5, lane = t & 31;
    const int i = blockIdx.x * 8 + w;            // sample handled by this warp
    const int my = sl[i];
    int r = 0, tot = 0;
#pragma unroll 4
    for (int j = lane; j < NSAMP; j += 32) {
        int eq = (sl[j] == my) ? 1 : 0;
        tot += eq;
        r += (j < i) ? eq : 0;
    }
#pragma unroll
    for (int o = 16; o; o >>= 1) {
        r   += __shfl_xor_sync(0xffffffffu, r, o);
        tot += __shfl_xor_sync(0xffffffffu, tot, o);
    }
    if (lane == 0) {
        if (r == 0) g_cnt[my] = tot;             // exactly one writer per class
        if (r < MAXDUP) g_bucket[my * MAXDUP + r] = i;
    }
}

// ============================================================
// asm helpers
// ============================================================
__device__ __forceinline__ void mma_f16(float c[4],
    unsigned a0, unsigned a1, unsigned a2, unsigned a3,
    unsigned b0, unsigned b1)
{
    asm volatile(
        "mma.sync.aligned.m16n8k16.row.col.f32.f16.f16.f32 "
        "{%0,%1,%2,%3},{%4,%5,%6,%7},{%8,%9},{%0,%1,%2,%3};\n"
        : "+f"(c[0]), "+f"(c[1]), "+f"(c[2]), "+f"(c[3])
        : "r"(a0), "r"(a1), "r"(a2), "r"(a3), "r"(b0), "r"(b1));
}

__device__ __forceinline__ void cp_async16(void* dst, const void* src)
{
    unsigned s = (unsigned)__cvta_generic_to_shared(dst);
    asm volatile("cp.async.cg.shared.global [%0], [%1], 16;\n" :: "r"(s), "l"(src));
}
__device__ __forceinline__ void cp_commit() { asm volatile("cp.async.commit_group;\n"); }
template<int W>
__device__ __forceinline__ void cp_wait() { asm volatile("cp.async.wait_group %0;\n" :: "n"(W) : "memory"); }

__device__ __forceinline__ void ldsm_x4(unsigned& r0, unsigned& r1,
                                        unsigned& r2, unsigned& r3, const void* p)
{
    unsigned a = (unsigned)__cvta_generic_to_shared(p);
    asm volatile("ldmatrix.sync.aligned.m8n8.x4.shared.b16 {%0,%1,%2,%3}, [%4];\n"
        : "=r"(r0), "=r"(r1), "=r"(r2), "=r"(r3) : "r"(a));
}

// ============================================================
// pipelined fp16 MMA GEMM: 128x128 block, BK=64, warp tile 64x32,
// 2-stage dynamic-smem cp.async pipeline, ONE barrier per k-iter.
// (safe: top barrier at iter kt is reached only after all warps finished
//  iter kt-1's compute on stage s^1, so loads into s^1 can't race it)
// WHICH: 0 = gemm1 -> g_hpart[z] ; 1 = sim -> Cout ; 2 = gemm2 -> g_fpart[z]
// ============================================================
#define GEMM_SMEM (2 * 36864)

template<int KP, int NK, int WHICH>
__global__ __launch_bounds__(256, 2) void mma_gemm_kernel(float* __restrict__ Cout)
{
    constexpr int BK = 64;
    constexpr int LDS_ = 72;
    constexpr int WTN = 32;
    constexpr int NTI = 4;
    constexpr int STG = 18432;
    constexpr int BOFF = 9216;
    constexpr int Nreal = (WHICH == 0) ? DMLP : (WHICH == 1 ? NCLS : FD);
    constexpr int ldc   = Nreal;

    const __half* __restrict__ A =
        (WHICH == 0) ? g_A1 : (WHICH == 1 ? g_feat2 : g_A2);
    const __half* __restrict__ B =
        (WHICH == 0) ? g_B1 : (WHICH == 1 ? g_mem2 : g_B2);
    float* __restrict__ C =
        (WHICH == 0) ? g_hpart[blockIdx.z] : (WHICH == 1 ? Cout : g_fpart[blockIdx.z]);

    const int ktb = (WHICH == 1) ? 0 : blockIdx.z * NK;

    extern __shared__ __align__(16) __half sm[];

    const int tid = threadIdx.x;
    const int wid = tid >> 5, lane = tid & 31;
    const int wm = wid >> 2, wn = wid & 3;
    const int bm = blockIdx.y * 128;
    const int bn = blockIdx.x * 128;

    const int lr0 = tid >> 3, lch = (tid & 7) * 8;
    auto load_stage = [&](int kt, int s) {
        __half* as = sm + s * STG;
        __half* bs = sm + s * STG + BOFF;
        const int kc = (ktb + kt) * BK + lch;
#pragma unroll
        for (int i = 0; i < 4; i++) {
            int r = lr0 + 32 * i;
            cp_async16(as + r * LDS_ + lch, A + (size_t)(bm + r) * KP + kc);
        }
#pragma unroll
        for (int i = 0; i < 4; i++) {
            int r = lr0 + 32 * i;
            int gn = bn + r;
            if (WHICH == 1) gn = (gn < NCLS) ? gn : (NCLS - 1);
            cp_async16(bs + r * LDS_ + lch, B + (size_t)gn * KP + kc);
        }
        cp_commit();
    };

    float acc[4][NTI][4];
#pragma unroll
    for (int i = 0; i < 4; i++)
#pragma unroll
        for (int j = 0; j < NTI; j++)
#pragma unroll
            for (int t = 0; t < 4; t++) acc[i][j][t] = 0.f;

    load_stage(0, 0);

    const int arow = lane & 15, ahalf = (lane >> 4) * 8;
    const int bl = lane & 7, bsel = lane >> 3;

    for (int kt = 0; kt < NK; kt++) {
        const int s = kt & 1;
        cp_wait<0>();
        __syncthreads();

        if (kt + 1 < NK) load_stage(kt + 1, s ^ 1);

        const __half* as = sm + s * STG;
        const __half* bs = sm + s * STG + BOFF;
#pragma unroll
        for (int ks = 0; ks < 4; ks++) {
            const int k0 = ks * 16;
            unsigned af[4][4];
#pragma unroll
            for (int i = 0; i < 4; i++)
                ldsm_x4(af[i][0], af[i][1], af[i][2], af[i][3],
                        as + (wm * 64 + i * 16 + arow) * LDS_ + k0 + ahalf);
            unsigned bfr[NTI][2];
#pragma unroll
            for (int p = 0; p < NTI / 2; p++) {
                int n = wn * WTN + (p * 2 + (bsel >> 1)) * 8 + bl;
                ldsm_x4(bfr[p * 2][0], bfr[p * 2][1], bfr[p * 2 + 1][0], bfr[p * 2 + 1][1],
                        bs + n * LDS_ + k0 + (bsel & 1) * 8);
            }
#pragma unroll
            for (int i = 0; i < 4; i++)
#pragma unroll
                for (int j = 0; j < NTI; j++)
                    mma_f16(acc[i][j], af[i][0], af[i][1], af[i][2], af[i][3],
                            bfr[j][0], bfr[j][1]);
        }
    }

    const int g = lane >> 2, q2 = (lane & 3) * 2;
#pragma unroll
    for (int i = 0; i < 4; i++) {
        int m0 = bm + wm * 64 + i * 16 + g;
#pragma unroll
        for (int j = 0; j < NTI; j++) {
            int n0 = bn + wn * WTN + j * 8 + q2;
            if (WHICH != 1 || n0 < Nreal) {
                *(float2*)(C + (size_t)m0 * ldc + n0) =
                    make_float2(acc[i][j][0], acc[i][j][1]);
                *(float2*)(C + (size_t)(m0 + 8) * ldc + n0) =
                    make_float2(acc[i][j][2], acc[i][j][3]);
            }
        }
    }
}

// ============================================================
// split-K reduce (x4) + b1 bias + BN partial stats
// ============================================================
__global__ __launch_bounds__(512) void bn_reduce_partial_kernel(
    const float* __restrict__ b1)
{
    const int b = blockIdx.x, c = threadIdx.x;
    const float bias = b1[c];
    float s = 0.f, ss = 0.f;
#pragma unroll
    for (int r = 0; r < 16; r++) {
        size_t i = (size_t)(b * 16 + r) * DMLP + c;
        float v = g_hpart[0][i] + g_hpart[1][i] + g_hpart[2][i] + g_hpart[3][i] + bias;
        g_h[i] = v;
        s += v; ss += v * v;
    }
    g_psum[b * DMLP + c] = s;
    g_psq[b * DMLP + c] = ss;
}

__global__ __launch_bounds__(512) void bn_final_kernel(
    const float* __restrict__ gamma, const float* __restrict__ beta)
{
    const int c = threadIdx.x;
    float s = 0.f, ss = 0.f;
#pragma unroll 8
    for (int b = 0; b < 256; b++) { s += g_psum[b * DMLP + c]; ss += g_psq[b * DMLP + c]; }
    float mu = s * (1.0f / NSAMP);
    float var = ss * (1.0f / NSAMP) - mu * mu;
    float sc = gamma[c] * rsqrtf(var + 1e-5f);
    g_scale[c] = sc;
    g_shift[c] = beta[c] - mu * sc;
}

// ============================================================
// gemm2 split-K reduce + b2 bias + L2 norm + write g_feat & fp16 g_feat2
// ============================================================
__global__ __launch_bounds__(256) void norm_kernel(const float* __restrict__ b2)
{
    const int w = threadIdx.x >> 5, lane = threadIdx.x & 31;
    const int row = blockIdx.x * 8 + w;
    const size_t off = (size_t)row * FD;
    float vals[8];
    float ssq = 0.f;
#pragma unroll
    for (int j = 0; j < 8; j++) {
        int k = (j < 4) ? lane * 4 + j : 128 + lane * 4 + (j - 4);
        float v = g_fpart[0][off + k] + g_fpart[1][off + k]
                + g_fpart[2][off + k] + g_fpart[3][off + k] + b2[k];
        vals[j] = v;
        ssq += v * v;
    }
#pragma unroll
    for (int o = 16; o; o >>= 1) ssq += __shfl_xor_sync(0xffffffffu, ssq, o);
    float inv = 1.0f / fmaxf(sqrtf(ssq), 1e-12f);
#pragma unroll
    for (int j = 0; j < 8; j++) vals[j] *= inv;
    float* p = g_feat + off;
    *(float4*)(p + lane * 4)       = make_float4(vals[0], vals[1], vals[2], vals[3]);
    *(float4*)(p + 128 + lane * 4) = make_float4(vals[4], vals[5], vals[6], vals[7]);
    __half* q = g_feat2 + off;
#pragma unroll
    for (int j = 0; j < 8; j++) {
        int k = (j < 4) ? lane * 4 + j : 128 + lane * 4 + (j - 4);
        q[k] = __float2half_rn(vals[j]);
    }
}

// ============================================================
// Memory update via inverted index: warp per class, walk own sample list
// ============================================================
__global__ __launch_bounds__(256) void memupd_kernel(const float* __restrict__ mem0)
{
    const int w = threadIdx.x >> 5, lane = threadIdx.x & 31;
    const int k = blockIdx.x * 8 + w;
    if (k >= NCLS) return;

    float pt[8];
#pragma unroll
    for (int j = 0; j < 8; j++) pt[j] = mem0[(size_t)k * FD + lane + j * 32];

    const int n = g_cnt[k];
    for (int r = 0; r < n; r++) {
        int i = g_bucket[k * MAXDUP + r];
        const float* f = g_feat + (size_t)i * FD;
        float ssq = 0.f;
#pragma unroll
        for (int j = 0; j < 8; j++) {
            pt[j] = 0.9f * pt[j] + 0.1f * f[lane + j * 32];
            ssq += pt[j] * pt[j];
        }
#pragma unroll
        for (int o = 16; o; o >>= 1) ssq += __shfl_xor_sync(0xffffffffu, ssq, o);
        float inv = 1.0f / fmaxf(sqrtf(ssq), 1e-12f);
#pragma unroll
        for (int j = 0; j < 8; j++) pt[j] *= inv;
    }
    __half* q = g_mem2 + (size_t)k * KPS;
#pragma unroll
    for (int j = 0; j < 8; j++) q[lane + j * 32] = __float2half_rn(pt[j]);
}

// ============================================================
// launch
// ============================================================
extern "C" void kernel_launch(void* const* d_in, const int* in_sizes, int n_in,
                              void* d_out, int out_size)
{
    const float* feat_in = (const float*)d_in[0];
    const int*   label   = (const int*)d_in[1];
    const float* W1      = (const float*)d_in[2];
    const float* b1      = (const float*)d_in[3];
    const float* gamma   = (const float*)d_in[4];
    const float* beta    = (const float*)d_in[5];
    const float* W2      = (const float*)d_in[6];
    const float* b2      = (const float*)d_in[7];
    const float* mem0    = (const float*)d_in[8];
    float* out = (float*)d_out;

    cudaFuncSetAttribute(mma_gemm_kernel<KP1, 6, 0>,
                         cudaFuncAttributeMaxDynamicSharedMemorySize, GEMM_SMEM);
    cudaFuncSetAttribute(mma_gemm_kernel<KP2, 2, 2>,
                         cudaFuncAttributeMaxDynamicSharedMemorySize, GEMM_SMEM);
    cudaFuncSetAttribute(mma_gemm_kernel<KPS, 4, 1>,
                         cudaFuncAttributeMaxDynamicSharedMemorySize, GEMM_SMEM);

    conv_A1_kernel<<<(NSAMP * DIN + 255) / 256, 256>>>(feat_in);   // + zero g_cnt
    convT_kernel<DIN, DMLP, 0><<<dim3(DMLP / 32, DIN / 32), 256>>>(W1);
    convT_kernel<DMLP, FD, 1><<<dim3(FD / 32, DMLP / 32), 256>>>(W2);
    rank_kernel<<<NSAMP / 8, 256>>>(label);

    // GEMM1 split-K x4 (fp16, BK=64): NK = 1536/(4*64) = 6
    mma_gemm_kernel<KP1, 6, 0>
        <<<dim3(DMLP / 128, NSAMP / 128, 4), 256, GEMM_SMEM>>>(nullptr);

    bn_reduce_partial_kernel<<<256, 512>>>(b1);
    bn_final_kernel<<<1, 512>>>(gamma, beta);
    conv_A2_kernel<<<(NSAMP * DMLP + 255) / 256, 256>>>();

    // GEMM2 split-K x4 (fp16, BK=64): NK = 512/(4*64) = 2
    mma_gemm_kernel<KP2, 2, 2>
        <<<dim3(FD / 128, NSAMP / 128, 4), 256, GEMM_SMEM>>>(nullptr);
    norm_kernel<<<NSAMP / 8, 256>>>(b2);

    memupd_kernel<<<(NCLS + 7) / 8, 256>>>(mem0);

    // Sim GEMM (fp16, BK=64): NK = 256/64 = 4
    mma_gemm_kernel<KPS, 4, 1>
        <<<dim3((NCLS + 127) / 128, NSAMP / 128, 1), 256, GEMM_SMEM>>>(out);
}